// round 15
// baseline (speedup 1.0000x reference)
#include <cuda_runtime.h>
#include <cuda_bf16.h>

#define HIMG 240
#define WIMG 135
#define HW   (HIMG * WIMG)
#define NF   1000
#define NV   600
#define INV_SIGMA 1.0e4f
#define BLURF 9.210240366975849e-4f
#define BAND  0.05f
#define SATURATE (-1.0e30f)        // log-space "covered"; exp -> 0, alpha -> 1

#define NT     512                 // 16 warps
#define SPLIT  2                   // row-slices per face
#define NRAST  (NF * SPLIT)        // 2000 raster blocks

struct __align__(16) FD {
    float ax, ay, bx, by, cx, cy;
    float e0x, e0y, e1x, e1y, e2x, e2y;
    float rl0, rl1, rl2, rd0, rd1, rd2;
    int x0, x1, y0, y1;
    int skip;
};

__device__ float g_sum[HW];   // zero at module load; finalize self-cleans

// ---------------------------------------------------------------------------
// Raster: grid NF*SPLIT, 16 warps/block. Block (f, sl) rasters rows of f's
// bbox with (row - y0) % 2 == sl. Setup once per block in warp 0.
// ---------------------------------------------------------------------------
__global__ void __launch_bounds__(NT)
raster_kernel(const float* __restrict__ verts,
              const int*   __restrict__ faces,
              float* __restrict__ out) {
    __shared__ FD sfd;

    const int tid  = threadIdx.x;
    const int lane = tid & 31;
    const int warp = tid >> 5;                  // 0..15
    const int bid  = blockIdx.x;
    const int f    = bid >> 1;                  // SPLIT == 2
    const int sl   = bid & 1;

    if (bid == 0 && tid == 0) out[0] = 0.0f;    // loss accumulator

    // ---- setup: warp 0 only (broadcast loads), smem publish ----
    if (warp == 0) {
        int idx[3];
        idx[0] = faces[3 * f + 0];
        idx[1] = faces[3 * f + 1];
        idx[2] = faces[3 * f + 2];

        float Px[3], Py[3], zs[3];
#pragma unroll
        for (int k = 0; k < 3; k++) {
            float x = verts[3 * idx[k] + 0];
            float y = verts[3 * idx[k] + 1];
            float z = verts[3 * idx[k] + 2];
            float vx = -x, vy = -y, vz = z;     // R = diag(-1,-1,1)
            zs[k] = vz;
            float zz = fmaxf(vz, 1e-6f);
            Px[k] = (__fdividef(1000.0f * vx, zz) + 512.0f) * ((float)WIMG / 1024.0f);
            Py[k] = (__fdividef(1000.0f * vy, zz) + 512.0f) * ((float)HIMG / 1024.0f);
        }
        float tz = (zs[0] + zs[1] + zs[2]) * (1.0f / 3.0f);

        FD fd;
        fd.ax = Px[0]; fd.ay = Py[0];
        fd.bx = Px[1]; fd.by = Py[1];
        fd.cx = Px[2]; fd.cy = Py[2];
        fd.e0x = fd.bx - fd.ax; fd.e0y = fd.by - fd.ay;
        fd.e1x = fd.cx - fd.bx; fd.e1y = fd.cy - fd.by;
        fd.e2x = fd.ax - fd.cx; fd.e2y = fd.ay - fd.cy;
        float l0 = fd.e0x * fd.e0x + fd.e0y * fd.e0y + 1e-12f;
        float l1 = fd.e1x * fd.e1x + fd.e1y * fd.e1y + 1e-12f;
        float l2 = fd.e2x * fd.e2x + fd.e2y * fd.e2y + 1e-12f;
        fd.rl0 = rsqrtf(l0); fd.rl1 = rsqrtf(l1); fd.rl2 = rsqrtf(l2);
        fd.rd0 = fd.rl0 * fd.rl0;
        fd.rd1 = fd.rl1 * fd.rl1;
        fd.rd2 = fd.rl2 * fd.rl2;

        fd.skip = !(tz > 1e-6f);
        if (!fd.skip) {
            float minx = fminf(fd.ax, fminf(fd.bx, fd.cx));
            float maxx = fmaxf(fd.ax, fmaxf(fd.bx, fd.cx));
            float miny = fminf(fd.ay, fminf(fd.by, fd.cy));
            float maxy = fmaxf(fd.ay, fmaxf(fd.by, fd.cy));
            fd.x0 = max(0, (int)floorf(minx) - 1);
            fd.x1 = min(WIMG - 1, (int)ceilf(maxx));
            fd.y0 = max(0, (int)floorf(miny) - 1);
            fd.y1 = min(HIMG - 1, (int)ceilf(maxy));
            // point-degenerate face: reference marks every pixel inside
            if (fd.e0x == 0.0f && fd.e0y == 0.0f &&
                fd.e1x == 0.0f && fd.e1y == 0.0f) {
                fd.x0 = 0; fd.x1 = WIMG - 1; fd.y0 = 0; fd.y1 = HIMG - 1;
            }
        } else {
            fd.x0 = 1; fd.x1 = 0; fd.y0 = 1; fd.y1 = 0;
        }
        if (lane == 0) sfd = fd;
    }
    __syncthreads();
    const FD fd = sfd;
    if (fd.skip) return;

    // ---- sweep rows with (row - y0) % 2 == sl; 16 warps stride 32 rows ----
    const int nrows = fd.y1 - fd.y0 + 1;
    for (int r = sl + warp * SPLIT; r < nrows; r += 16 * SPLIT) {
        int   iy  = fd.y0 + r;
        float py  = (float)iy + 0.5f;
        int   row = iy * WIMG;
        for (int ix = fd.x0 + lane; ix <= fd.x1; ix += 32) {
            float px = (float)ix + 0.5f;

            float apx0 = px - fd.ax, apy0 = py - fd.ay;
            float apx1 = px - fd.bx, apy1 = py - fd.by;
            float apx2 = px - fd.cx, apy2 = py - fd.cy;

            float c0 = fd.e0x * apy0 - fd.e0y * apx0;
            float c1 = fd.e1x * apy1 - fd.e1y * apx1;
            float c2 = fd.e2x * apy2 - fd.e2y * apx2;
            bool inside = (c0 >= 0.0f && c1 >= 0.0f && c2 >= 0.0f) ||
                          (c0 <= 0.0f && c1 <= 0.0f && c2 <= 0.0f);

            // conservative perpendicular line distance (<= segment distance)
            float dl = fminf(fabsf(c0) * fd.rl0,
                       fminf(fabsf(c1) * fd.rl1, fabsf(c2) * fd.rl2));

            if (inside && dl > BAND) {
                // log contribution <= -25: alpha saturates to 1. All other
                // contributions are negative, so any ST/RED interleaving
                // leaves s <= -25 -> expf(s) == 0.
                __stcg(&g_sum[row + ix], SATURATE);
            } else if (inside || dl <= BAND) {
                // exact reference math (segment distances)
                float t0 = fminf(fmaxf((apx0 * fd.e0x + apy0 * fd.e0y) * fd.rd0, 0.0f), 1.0f);
                float rx = apx0 - t0 * fd.e0x;
                float ry = apy0 - t0 * fd.e0y;
                float d2min = rx * rx + ry * ry;

                float t1 = fminf(fmaxf((apx1 * fd.e1x + apy1 * fd.e1y) * fd.rd1, 0.0f), 1.0f);
                rx = apx1 - t1 * fd.e1x;
                ry = apy1 - t1 * fd.e1y;
                d2min = fminf(d2min, rx * rx + ry * ry);

                float t2 = fminf(fmaxf((apx2 * fd.e2x + apy2 * fd.e2y) * fd.rd2, 0.0f), 1.0f);
                rx = apx2 - t2 * fd.e2x;
                ry = apy2 - t2 * fd.e2y;
                d2min = fminf(d2min, rx * rx + ry * ry);

                if (inside || d2min <= BLURF) {
                    float u = (inside ? d2min : -d2min) * INV_SIGMA;
                    // log1p(-sigmoid(u)) == -softplus(u)
                    float sp = (u > 15.0f) ? u : log1pf(__expf(u));
                    if (sp != 0.0f) atomicAdd(&g_sum[row + ix], -sp);
                }
            }
            // outside & dl > BAND: d2min >= dl^2 > BLURF -> reference-invalid
        }
    }
}

// ---------------------------------------------------------------------------
// Finalize (PDL): alpha = 1 - exp(s); sil + loss; self-cleans g_sum.
// ---------------------------------------------------------------------------
__global__ void __launch_bounds__(256)
finalize_kernel(const float* __restrict__ gt,
                float* __restrict__ out) {
    cudaGridDependencySynchronize();             // raster grid complete

    int i = blockIdx.x * blockDim.x + threadIdx.x;
    float local = 0.0f;
    if (i < HW) {
        float s = g_sum[i];
        g_sum[i] = 0.0f;                         // self-clean for replay
        float alpha = 1.0f - expf(s);            // s=SATURATE -> alpha=1
        out[1 + i] = alpha;
        local = fabsf(alpha - gt[i]);
    }
#pragma unroll
    for (int o = 16; o > 0; o >>= 1)
        local += __shfl_down_sync(0xffffffffu, local, o);

    __shared__ float ws[8];
    int lane = threadIdx.x & 31;
    int wid  = threadIdx.x >> 5;
    if (lane == 0) ws[wid] = local;
    __syncthreads();
    if (wid == 0) {
        local = (lane < 8) ? ws[lane] : 0.0f;
#pragma unroll
        for (int o = 4; o > 0; o >>= 1)
            local += __shfl_down_sync(0xffu, local, o);
        if (lane == 0)
            atomicAdd(out, local * (1.0f / (float)HW));
    }
}

// ---------------------------------------------------------------------------
extern "C" void kernel_launch(void* const* d_in, const int* in_sizes, int n_in,
                              void* d_out, int out_size) {
    const float* verts = nullptr;
    const float* gt    = nullptr;
    const int*   faces = nullptr;
    for (int i = 0; i < n_in; i++) {
        if (in_sizes[i] == NV * 3)      verts = (const float*)d_in[i];
        else if (in_sizes[i] == HW)     gt    = (const float*)d_in[i];
        else if (in_sizes[i] == NF * 3) faces = (const int*)d_in[i];
    }
    float* out = (float*)d_out;
    (void)out_size;

    raster_kernel<<<NRAST, NT>>>(verts, faces, out);

    // PDL: overlap finalize's launch latency with raster execution.
    cudaLaunchConfig_t cfg = {};
    cfg.blockDim = dim3(256, 1, 1);
    cfg.gridDim  = dim3((HW + 255) / 256, 1, 1);
    cfg.stream   = 0;
    cudaLaunchAttribute attrs[1];
    attrs[0].id = cudaLaunchAttributeProgrammaticStreamSerialization;
    attrs[0].val.programmaticStreamSerializationAllowed = 1;
    cfg.attrs    = attrs;
    cfg.numAttrs = 1;
    cudaLaunchKernelEx(&cfg, finalize_kernel, gt, out);
}

// round 16
// speedup vs baseline: 1.1248x; 1.1248x over previous
#include <cuda_runtime.h>
#include <cuda_bf16.h>

#define HIMG 240
#define WIMG 135
#define HW   (HIMG * WIMG)
#define NF   1000
#define NV   600
#define INV_SIGMA 1.0e4f
#define BLURF 9.210240366975849e-4f
#define BAND  0.05f
#define SATURATE (-1.0e30f)        // log-space "covered"; exp -> 0, alpha -> 1

#define NT     128                 // 4 warps
#define SPLIT  8                   // row-slices per face
#define NRAST  (NF * SPLIT)        // 8000 raster blocks

struct __align__(16) FD {
    float ax, ay, bx, by, cx, cy;
    float e0x, e0y, e1x, e1y, e2x, e2y;
    float rl0, rl1, rl2, rd0, rd1, rd2;
    int x0, x1, y0, y1;
    int skip;
};

__device__ float g_sum[HW];   // zero at module load; finalize self-cleans

// ---------------------------------------------------------------------------
// Raster: grid NF*SPLIT. Block handles rows of its face whose bbox-relative
// index === slice (mod SPLIT). Setup once per block (warp 0 -> smem).
// ---------------------------------------------------------------------------
__global__ void __launch_bounds__(NT)
raster_kernel(const float* __restrict__ verts,
              const int*   __restrict__ faces,
              float* __restrict__ out) {
    __shared__ FD sfd;

    const int tid  = threadIdx.x;
    const int lane = tid & 31;
    const int warp = tid >> 5;                  // 0..3
    const int bid  = blockIdx.x;
    const int f    = bid >> 3;                  // SPLIT == 8
    const int sl   = bid & 7;

    if (bid == 0 && tid == 0) out[0] = 0.0f;    // loss accumulator

    // ---- setup: warp 0 only (broadcast loads), smem publish ----
    if (warp == 0) {
        int idx[3];
        idx[0] = faces[3 * f + 0];
        idx[1] = faces[3 * f + 1];
        idx[2] = faces[3 * f + 2];

        float Px[3], Py[3], zs[3];
#pragma unroll
        for (int k = 0; k < 3; k++) {
            float x = verts[3 * idx[k] + 0];
            float y = verts[3 * idx[k] + 1];
            float z = verts[3 * idx[k] + 2];
            float vx = -x, vy = -y, vz = z;     // R = diag(-1,-1,1)
            zs[k] = vz;
            float zz = fmaxf(vz, 1e-6f);
            Px[k] = (__fdividef(1000.0f * vx, zz) + 512.0f) * ((float)WIMG / 1024.0f);
            Py[k] = (__fdividef(1000.0f * vy, zz) + 512.0f) * ((float)HIMG / 1024.0f);
        }
        float tz = (zs[0] + zs[1] + zs[2]) * (1.0f / 3.0f);

        FD fd;
        fd.ax = Px[0]; fd.ay = Py[0];
        fd.bx = Px[1]; fd.by = Py[1];
        fd.cx = Px[2]; fd.cy = Py[2];
        fd.e0x = fd.bx - fd.ax; fd.e0y = fd.by - fd.ay;
        fd.e1x = fd.cx - fd.bx; fd.e1y = fd.cy - fd.by;
        fd.e2x = fd.ax - fd.cx; fd.e2y = fd.ay - fd.cy;
        float l0 = fd.e0x * fd.e0x + fd.e0y * fd.e0y + 1e-12f;
        float l1 = fd.e1x * fd.e1x + fd.e1y * fd.e1y + 1e-12f;
        float l2 = fd.e2x * fd.e2x + fd.e2y * fd.e2y + 1e-12f;
        fd.rl0 = rsqrtf(l0); fd.rl1 = rsqrtf(l1); fd.rl2 = rsqrtf(l2);
        fd.rd0 = fd.rl0 * fd.rl0;
        fd.rd1 = fd.rl1 * fd.rl1;
        fd.rd2 = fd.rl2 * fd.rl2;

        fd.skip = !(tz > 1e-6f);
        if (!fd.skip) {
            float minx = fminf(fd.ax, fminf(fd.bx, fd.cx));
            float maxx = fmaxf(fd.ax, fmaxf(fd.bx, fd.cx));
            float miny = fminf(fd.ay, fminf(fd.by, fd.cy));
            float maxy = fmaxf(fd.ay, fmaxf(fd.by, fd.cy));
            fd.x0 = max(0, (int)floorf(minx) - 1);
            fd.x1 = min(WIMG - 1, (int)ceilf(maxx));
            fd.y0 = max(0, (int)floorf(miny) - 1);
            fd.y1 = min(HIMG - 1, (int)ceilf(maxy));
            // point-degenerate face: reference marks every pixel inside
            if (fd.e0x == 0.0f && fd.e0y == 0.0f &&
                fd.e1x == 0.0f && fd.e1y == 0.0f) {
                fd.x0 = 0; fd.x1 = WIMG - 1; fd.y0 = 0; fd.y1 = HIMG - 1;
            }
        } else {
            fd.x0 = 1; fd.x1 = 0; fd.y0 = 1; fd.y1 = 0;
        }
        if (lane == 0) sfd = fd;
    }
    __syncthreads();
    const FD fd = sfd;
    if (fd.skip) return;

    // ---- sweep rows with (row - y0) % SPLIT == sl; 4 warps stride --------
    const int nrows = fd.y1 - fd.y0 + 1;
    for (int r = sl + warp * SPLIT; r < nrows; r += 4 * SPLIT) {
        int   iy  = fd.y0 + r;
        float py  = (float)iy + 0.5f;
        int   row = iy * WIMG;
        for (int ix = fd.x0 + lane; ix <= fd.x1; ix += 32) {
            float px = (float)ix + 0.5f;

            float apx0 = px - fd.ax, apy0 = py - fd.ay;
            float apx1 = px - fd.bx, apy1 = py - fd.by;
            float apx2 = px - fd.cx, apy2 = py - fd.cy;

            float c0 = fd.e0x * apy0 - fd.e0y * apx0;
            float c1 = fd.e1x * apy1 - fd.e1y * apx1;
            float c2 = fd.e2x * apy2 - fd.e2y * apx2;
            bool inside = (c0 >= 0.0f && c1 >= 0.0f && c2 >= 0.0f) ||
                          (c0 <= 0.0f && c1 <= 0.0f && c2 <= 0.0f);

            // conservative perpendicular line distance (<= segment distance)
            float dl = fminf(fabsf(c0) * fd.rl0,
                       fminf(fabsf(c1) * fd.rl1, fabsf(c2) * fd.rl2));

            if (inside && dl > BAND) {
                // log contribution <= -25: alpha saturates to 1. All other
                // contributions are negative, so any ST/RED interleaving
                // leaves s <= -25 -> expf(s) == 0.
                __stcg(&g_sum[row + ix], SATURATE);
            } else if (inside || dl <= BAND) {
                // exact reference math (segment distances)
                float t0 = fminf(fmaxf((apx0 * fd.e0x + apy0 * fd.e0y) * fd.rd0, 0.0f), 1.0f);
                float rx = apx0 - t0 * fd.e0x;
                float ry = apy0 - t0 * fd.e0y;
                float d2min = rx * rx + ry * ry;

                float t1 = fminf(fmaxf((apx1 * fd.e1x + apy1 * fd.e1y) * fd.rd1, 0.0f), 1.0f);
                rx = apx1 - t1 * fd.e1x;
                ry = apy1 - t1 * fd.e1y;
                d2min = fminf(d2min, rx * rx + ry * ry);

                float t2 = fminf(fmaxf((apx2 * fd.e2x + apy2 * fd.e2y) * fd.rd2, 0.0f), 1.0f);
                rx = apx2 - t2 * fd.e2x;
                ry = apy2 - t2 * fd.e2y;
                d2min = fminf(d2min, rx * rx + ry * ry);

                if (inside || d2min <= BLURF) {
                    float u = (inside ? d2min : -d2min) * INV_SIGMA;
                    // log1p(-sigmoid(u)) == -softplus(u)
                    float sp = (u > 15.0f) ? u : log1pf(__expf(u));
                    if (sp != 0.0f) atomicAdd(&g_sum[row + ix], -sp);
                }
            }
            // outside & dl > BAND: d2min >= dl^2 > BLURF -> reference-invalid
        }
    }
}

// ---------------------------------------------------------------------------
// Finalize (PDL): alpha = 1 - exp(s); sil + loss; self-cleans g_sum.
// ---------------------------------------------------------------------------
__global__ void __launch_bounds__(256)
finalize_kernel(const float* __restrict__ gt,
                float* __restrict__ out) {
    cudaGridDependencySynchronize();             // raster grid complete

    int i = blockIdx.x * blockDim.x + threadIdx.x;
    float local = 0.0f;
    if (i < HW) {
        float s = g_sum[i];
        g_sum[i] = 0.0f;                         // self-clean for replay
        float alpha = 1.0f - expf(s);            // s=SATURATE -> alpha=1
        out[1 + i] = alpha;
        local = fabsf(alpha - gt[i]);
    }
#pragma unroll
    for (int o = 16; o > 0; o >>= 1)
        local += __shfl_down_sync(0xffffffffu, local, o);

    __shared__ float ws[8];
    int lane = threadIdx.x & 31;
    int wid  = threadIdx.x >> 5;
    if (lane == 0) ws[wid] = local;
    __syncthreads();
    if (wid == 0) {
        local = (lane < 8) ? ws[lane] : 0.0f;
#pragma unroll
        for (int o = 4; o > 0; o >>= 1)
            local += __shfl_down_sync(0xffu, local, o);
        if (lane == 0)
            atomicAdd(out, local * (1.0f / (float)HW));
    }
}

// ---------------------------------------------------------------------------
extern "C" void kernel_launch(void* const* d_in, const int* in_sizes, int n_in,
                              void* d_out, int out_size) {
    const float* verts = nullptr;
    const float* gt    = nullptr;
    const int*   faces = nullptr;
    for (int i = 0; i < n_in; i++) {
        if (in_sizes[i] == NV * 3)      verts = (const float*)d_in[i];
        else if (in_sizes[i] == HW)     gt    = (const float*)d_in[i];
        else if (in_sizes[i] == NF * 3) faces = (const int*)d_in[i];
    }
    float* out = (float*)d_out;
    (void)out_size;

    raster_kernel<<<NRAST, NT>>>(verts, faces, out);

    // PDL: overlap finalize's launch latency with raster execution.
    cudaLaunchConfig_t cfg = {};
    cfg.blockDim = dim3(256, 1, 1);
    cfg.gridDim  = dim3((HW + 255) / 256, 1, 1);
    cfg.stream   = 0;
    cudaLaunchAttribute attrs[1];
    attrs[0].id = cudaLaunchAttributeProgrammaticStreamSerialization;
    attrs[0].val.programmaticStreamSerializationAllowed = 1;
    cfg.attrs    = attrs;
    cfg.numAttrs = 1;
    cudaLaunchKernelEx(&cfg, finalize_kernel, gt, out);
}